// round 9
// baseline (speedup 1.0000x reference)
#include <cuda_runtime.h>
#include <cstdint>

#define D4   64        // 256 floats = 64 float4 per input row
#define OD4  128       // 512 floats = 128 float4 per output row
#define TPB  128
#define NUM_GRAPHS 8192

// Graph boundaries: bound[g] = first row index with batch[i] >= g; bound[B] = n
__device__ int g_bound[NUM_GRAPHS + 1];

// ---------------------------------------------------------------------------
// Kernel 1 (R6 verbatim): boundary extraction, int4-vectorized, 4 elems/thread.
// ---------------------------------------------------------------------------
__global__ __launch_bounds__(256)
void bounds_kernel(const int* __restrict__ batch, int n)
{
    int t = blockIdx.x * blockDim.x + threadIdx.x;
    int i0 = t * 4;
    if (i0 >= n) return;

    int b[5];                         // batch[i0-1 .. i0+3] (clamped)
    b[0] = (i0 == 0) ? -1 : batch[i0 - 1];
    if (i0 + 4 <= n && (i0 & 3) == 0) {
        int4 v = *(const int4*)(batch + i0);
        b[1] = v.x; b[2] = v.y; b[3] = v.z; b[4] = v.w;
    } else {
        #pragma unroll
        for (int k = 0; k < 4; ++k)
            b[k + 1] = (i0 + k < n) ? batch[i0 + k] : -2;
    }

    #pragma unroll
    for (int k = 0; k < 4; ++k) {
        int i = i0 + k;
        if (i >= n) break;
        for (int g = b[k] + 1; g <= b[k + 1]; ++g) g_bound[g] = i;
        if (i == n - 1)
            for (int g = b[k + 1] + 1; g <= NUM_GRAPHS; ++g) g_bound[g] = n;
    }
}

// ---------------------------------------------------------------------------
// Kernel 2 (R7 verbatim): fused pool + assemble. One CTA (128 thr) per graph.
// Ungated (~80%): single streaming pass writes both halves (8 rows/iter).
// Gated: node-half pass accumulates masked column sums in-flight; parities
// combined via smem; short store-only pass writes the pool half.
// ---------------------------------------------------------------------------
__global__ __launch_bounds__(TPB, 16)
void fused_kernel(const float4* __restrict__ node4,
                  const int*    __restrict__ label,
                  float4*       __restrict__ out4)
{
    const int g   = blockIdx.x;
    const int tid = threadIdx.x;

    const int start = g_bound[g];          // L2-hot broadcast loads
    const int end   = g_bound[g + 1];
    if (start >= end) return;

    const int c = tid & 63;                // column (float4) within half-row
    const int r = tid >> 6;                // row parity within each 2-row tile

    const bool gate = (label[end - 1] == -1);

    if (!gate) {
        // ---------------- hot path: pool == 0, one pass ----------------
        const float4 zero = make_float4(0.f, 0.f, 0.f, 0.f);
        int i = start;
        for (; i + 8 <= end; i += 8) {
            float4 v0 = __ldcs(&node4[(size_t)(i    ) * D4 + tid]);
            float4 v1 = __ldcs(&node4[(size_t)(i + 2) * D4 + tid]);
            float4 v2 = __ldcs(&node4[(size_t)(i + 4) * D4 + tid]);
            float4 v3 = __ldcs(&node4[(size_t)(i + 6) * D4 + tid]);
            size_t rb0 = (size_t)(i     + r) * OD4;
            size_t rb1 = (size_t)(i + 2 + r) * OD4;
            size_t rb2 = (size_t)(i + 4 + r) * OD4;
            size_t rb3 = (size_t)(i + 6 + r) * OD4;
            __stcs(&out4[rb0 + c], v0);  __stcs(&out4[rb0 + 64 + c], zero);
            __stcs(&out4[rb1 + c], v1);  __stcs(&out4[rb1 + 64 + c], zero);
            __stcs(&out4[rb2 + c], v2);  __stcs(&out4[rb2 + 64 + c], zero);
            __stcs(&out4[rb3 + c], v3);  __stcs(&out4[rb3 + 64 + c], zero);
        }
        for (; i + 2 <= end; i += 2) {
            float4 v = __ldcs(&node4[(size_t)i * D4 + tid]);
            size_t rb = (size_t)(i + r) * OD4;
            __stcs(&out4[rb + c], v);
            __stcs(&out4[rb + 64 + c], zero);
        }
        if (i < end) {
            size_t rb = (size_t)i * OD4;
            if (r == 0) {
                float4 v = __ldcs(&node4[(size_t)i * D4 + c]);
                __stcs(&out4[rb + c], v);
            } else {
                __stcs(&out4[rb + 64 + c], zero);
            }
        }
        return;
    }

    // ---------------- gated path: accumulate during the node-half pass ----
    __shared__ __align__(16) float4 s_acc[TPB];
    __shared__ float s_cnt[2];

    float4 acc = make_float4(0.f, 0.f, 0.f, 0.f);
    float  cnt = 0.f;

    int i = start;
    #pragma unroll 2
    for (; i + 2 <= end; i += 2) {
        const int row = i + r;
        float4 v  = __ldcs(&node4[(size_t)i * D4 + tid]);   // rows i, i+1
        int   lbl = label[row];
        __stcs(&out4[(size_t)row * OD4 + c], v);
        if (lbl == -1) {
            acc.x += v.x; acc.y += v.y; acc.z += v.z; acc.w += v.w;
            cnt += 1.f;
        }
    }
    if (i < end && r == 0) {               // odd remainder row (node half)
        float4 v = __ldcs(&node4[(size_t)i * D4 + c]);
        __stcs(&out4[(size_t)i * OD4 + c], v);
        if (label[i] == -1) {
            acc.x += v.x; acc.y += v.y; acc.z += v.z; acc.w += v.w;
            cnt += 1.f;
        }
    }

    s_acc[tid] = acc;
    if (c == 0) s_cnt[r] = cnt;
    __syncthreads();

    float4 a0 = s_acc[c];
    float4 a1 = s_acc[64 + c];
    float  inv = 1.f / fmaxf(s_cnt[0] + s_cnt[1], 1.f);
    float4 poolv = make_float4((a0.x + a1.x) * inv, (a0.y + a1.y) * inv,
                               (a0.z + a1.z) * inv, (a0.w + a1.w) * inv);

    // store-only pool-half pass (~1KB/row)
    for (i = start; i + 2 <= end; i += 2)
        __stcs(&out4[(size_t)(i + r) * OD4 + 64 + c], poolv);
    if (i < end && r == 0)
        __stcs(&out4[(size_t)i * OD4 + 64 + c], poolv);
}

// ---------------------------------------------------------------------------
// Inputs: [node_rep f32 N*256, batch i32 N, primary_label i32 N, num_graphs]
// Output: f32 N*512.
// ---------------------------------------------------------------------------
extern "C" void kernel_launch(void* const* d_in, const int* in_sizes, int n_in,
                              void* d_out, int out_size)
{
    const float4* node4 = (const float4*)d_in[0];
    const int*    batch = (const int*)d_in[1];
    const int*    label = (const int*)d_in[2];
    const int     n     = in_sizes[1];

    int bthreads = (n + 3) / 4;
    bounds_kernel<<<(bthreads + 255) / 256, 256>>>(batch, n);
    fused_kernel<<<NUM_GRAPHS, TPB>>>(node4, label, (float4*)d_out);
}